// round 5
// baseline (speedup 1.0000x reference)
#include <cuda_runtime.h>
#include <math.h>

#define JN 24
#define EPSF 1e-8f
#define TPB 256

// Natural order 0..23 is a valid traversal (parents monotone) and emits the
// output floats sequentially -> rolling 4-float buffer -> 18 STG.128/thread.
// This round: cut register pressure (no blv[] array, launch_bounds cap) to
// lift occupancy from 34% to ~60% — the kernel is latency-bound, not
// bandwidth-bound (HBM traffic already at algorithmic minimum).

__global__ __launch_bounds__(TPB, 5) void fk_kernel(
    const float4* __restrict__ rootq,   // [B,4]  (w,x,y,z)
    const float*  __restrict__ rootp,   // [B,3]
    const float4* __restrict__ localq,  // [B,J,4]
    const float*  __restrict__ bl,      // [B,J]
    const float*  __restrict__ restd,   // [J,3]
    float*        __restrict__ out,     // [B,J,3]
    int nbatch)
{
    __shared__ float sdir[JN * 3];
    if (threadIdx.x < JN * 3) sdir[threadIdx.x] = restd[threadIdx.x];
    __syncthreads();

    const int b = blockIdx.x * TPB + threadIdx.x;
    if (b >= nbatch) return;

    const int PAR[JN] = {-1,0,0,0,1,2,3,4,5,6,7,8,9,9,9,12,13,14,16,17,18,19,20,21};

    float gqw[JN], gqx[JN], gqy[JN], gqz[JN];
    float gpx[JN], gpy[JN], gpz[JN];

    // Root: normalize orientation quat; position passes through.
    {
        float4 rq = rootq[b];
        float s   = rq.x*rq.x + rq.y*rq.y + rq.z*rq.z + rq.w*rq.w;
        float inv = 1.0f / (sqrtf(s) + EPSF);
        gqw[0] = rq.x * inv;
        gqx[0] = rq.y * inv;
        gqy[0] = rq.z * inv;
        gqz[0] = rq.w * inv;
    }
    gpx[0] = rootp[3 * b + 0];
    gpy[0] = rootp[3 * b + 1];
    gpz[0] = rootp[3 * b + 2];

    // Rolling 4-float output buffer -> STG.128 per 4 completed floats.
    float sb[4];
    float4* out4 = (float4*)out + (size_t)b * 18;

    #define EMIT(o, v)                                                   \
        do {                                                             \
            sb[(o) & 3] = (v);                                           \
            if (((o) & 3) == 3)                                          \
                out4[(o) >> 2] = make_float4(sb[0], sb[1], sb[2], sb[3]);\
        } while (0)

    EMIT(0, gpx[0]);
    EMIT(1, gpy[0]);
    EMIT(2, gpz[0]);

    const float4* lq  = localq + (size_t)b * JN;
    const float*  blb = bl     + (size_t)b * JN;

    #pragma unroll
    for (int j = 1; j < JN; j++) {
        const int p = PAR[j];

        // Normalize local quat for joint j.
        float4 c4 = lq[j];
        float s   = c4.x*c4.x + c4.y*c4.y + c4.z*c4.z + c4.w*c4.w;
        float inv = 1.0f / (sqrtf(s) + EPSF);
        float cw = c4.x * inv, cx = c4.y * inv, cy = c4.z * inv, cz = c4.w * inv;

        // Parent global quat.
        float pw = gqw[p], px = gqx[p], py = gqy[p], pz = gqz[p];

        // Global quat for j = parent . local.
        gqw[j] = pw*cw - px*cx - py*cy - pz*cz;
        gqx[j] = pw*cx + px*cw + py*cz - pz*cy;
        gqy[j] = pw*cy - px*cz + py*cw + pz*cx;
        gqz[j] = pw*cz + px*cy - py*cx + pz*cw;

        // Rotate rest direction d[j] by the PARENT quat:
        // t = 2*cross(qvec, d); r = d + qw*t + cross(qvec, t)
        float dx = sdir[3*j + 0], dy = sdir[3*j + 1], dz = sdir[3*j + 2];
        float tx = 2.0f * (py*dz - pz*dy);
        float ty = 2.0f * (pz*dx - px*dz);
        float tz = 2.0f * (px*dy - py*dx);
        float rx = dx + pw*tx + (py*tz - pz*ty);
        float ry = dy + pw*ty + (pz*tx - px*tz);
        float rz = dz + pw*tz + (px*ty - py*tx);

        float L = blb[j];          // scalar load at use-site (L1-resident line)
        gpx[j] = gpx[p] + rx * L;
        gpy[j] = gpy[p] + ry * L;
        gpz[j] = gpz[p] + rz * L;

        EMIT(3*j + 0, gpx[j]);
        EMIT(3*j + 1, gpy[j]);
        EMIT(3*j + 2, gpz[j]);
    }
    #undef EMIT
}

extern "C" void kernel_launch(void* const* d_in, const int* in_sizes, int n_in,
                              void* d_out, int out_size)
{
    // metadata order: root_orientation_quat [B,4], root_position [B,3],
    //                 local_joint_rotations_quat [B,J,4], bone_lengths [B,J],
    //                 rest_directions [J,3]
    const float4* rootq  = (const float4*)d_in[0];
    const float*  rootp  = (const float*)d_in[1];
    const float4* localq = (const float4*)d_in[2];
    const float*  bl     = (const float*)d_in[3];
    const float*  restd  = (const float*)d_in[4];
    float*        out    = (float*)d_out;

    int nbatch = in_sizes[1] / 3;   // root_position has B*3 elements

    int blocks = (nbatch + TPB - 1) / TPB;
    fk_kernel<<<blocks, TPB>>>(rootq, rootp, localq, bl, restd, out, nbatch);
}

// round 6
// speedup vs baseline: 1.6796x; 1.6796x over previous
#include <cuda_runtime.h>
#include <math.h>

#define JN 24
#define EPSF 1e-8f
#define TPB 256

// Natural order 0..23 is a valid traversal (parents monotone) and emits the
// output floats sequentially. Rolling 8-float register buffer -> 9 256-bit
// stores per thread (st.global.v8.f32, sm_100+): every store covers full
// 32B sectors, halving L2 store accesses and LSU issue cost vs float4.
// launch_bounds(256,4): target 64 regs -> 4 CTAs/SM (~47% occ) while keeping
// the load hoisting that R4 showed is the real performance driver.

__device__ __forceinline__ void stg256(float* p, const float* v) {
    asm volatile(
        "st.global.v8.f32 [%0], {%1,%2,%3,%4,%5,%6,%7,%8};"
        :: "l"(p),
           "f"(v[0]), "f"(v[1]), "f"(v[2]), "f"(v[3]),
           "f"(v[4]), "f"(v[5]), "f"(v[6]), "f"(v[7])
        : "memory");
}

__global__ __launch_bounds__(TPB, 4) void fk_kernel(
    const float4* __restrict__ rootq,   // [B,4]  (w,x,y,z)
    const float*  __restrict__ rootp,   // [B,3]
    const float4* __restrict__ localq,  // [B,J,4]
    const float*  __restrict__ bl,      // [B,J]
    const float*  __restrict__ restd,   // [J,3]
    float*        __restrict__ out,     // [B,J,3]
    int nbatch)
{
    __shared__ float sdir[JN * 3];
    if (threadIdx.x < JN * 3) sdir[threadIdx.x] = restd[threadIdx.x];
    __syncthreads();

    const int b = blockIdx.x * TPB + threadIdx.x;
    if (b >= nbatch) return;

    const int PAR[JN] = {-1,0,0,0,1,2,3,4,5,6,7,8,9,9,9,12,13,14,16,17,18,19,20,21};

    // Hoist all 24 bone lengths as 6 independent float4 loads (MLP).
    float blv[JN];
    {
        const float4* bl4 = (const float4*)(bl + (size_t)b * JN);
        #pragma unroll
        for (int i = 0; i < 6; i++) {
            float4 v = bl4[i];
            blv[4*i + 0] = v.x; blv[4*i + 1] = v.y;
            blv[4*i + 2] = v.z; blv[4*i + 3] = v.w;
        }
    }

    float gqw[JN], gqx[JN], gqy[JN], gqz[JN];
    float gpx[JN], gpy[JN], gpz[JN];

    // Root: normalize orientation quat; position passes through.
    {
        float4 rq = rootq[b];
        float s   = rq.x*rq.x + rq.y*rq.y + rq.z*rq.z + rq.w*rq.w;
        float inv = 1.0f / (sqrtf(s) + EPSF);
        gqw[0] = rq.x * inv;
        gqx[0] = rq.y * inv;
        gqy[0] = rq.z * inv;
        gqz[0] = rq.w * inv;
    }
    gpx[0] = rootp[3 * b + 0];
    gpy[0] = rootp[3 * b + 1];
    gpz[0] = rootp[3 * b + 2];

    // Rolling 8-float output buffer -> one st.global.v8.f32 per 8 floats.
    float sb[8];
    float* ob = out + (size_t)b * (JN * 3);

    #define EMIT(o, v)                                 \
        do {                                           \
            sb[(o) & 7] = (v);                         \
            if (((o) & 7) == 7)                        \
                stg256(ob + ((o) & ~7), sb);           \
        } while (0)

    EMIT(0, gpx[0]);
    EMIT(1, gpy[0]);
    EMIT(2, gpz[0]);

    const float4* lq = localq + (size_t)b * JN;

    #pragma unroll
    for (int j = 1; j < JN; j++) {
        const int p = PAR[j];

        // Normalize local quat for joint j.
        float4 c4 = lq[j];
        float s   = c4.x*c4.x + c4.y*c4.y + c4.z*c4.z + c4.w*c4.w;
        float inv = 1.0f / (sqrtf(s) + EPSF);
        float cw = c4.x * inv, cx = c4.y * inv, cy = c4.z * inv, cz = c4.w * inv;

        // Parent global quat.
        float pw = gqw[p], px = gqx[p], py = gqy[p], pz = gqz[p];

        // Global quat for j = parent . local.
        gqw[j] = pw*cw - px*cx - py*cy - pz*cz;
        gqx[j] = pw*cx + px*cw + py*cz - pz*cy;
        gqy[j] = pw*cy - px*cz + py*cw + pz*cx;
        gqz[j] = pw*cz + px*cy - py*cx + pz*cw;

        // Rotate rest direction d[j] by the PARENT quat:
        // t = 2*cross(qvec, d); r = d + qw*t + cross(qvec, t)
        float dx = sdir[3*j + 0], dy = sdir[3*j + 1], dz = sdir[3*j + 2];
        float tx = 2.0f * (py*dz - pz*dy);
        float ty = 2.0f * (pz*dx - px*dz);
        float tz = 2.0f * (px*dy - py*dx);
        float rx = dx + pw*tx + (py*tz - pz*ty);
        float ry = dy + pw*ty + (pz*tx - px*tz);
        float rz = dz + pw*tz + (px*ty - py*tx);

        float L = blv[j];
        gpx[j] = gpx[p] + rx * L;
        gpy[j] = gpy[p] + ry * L;
        gpz[j] = gpz[p] + rz * L;

        EMIT(3*j + 0, gpx[j]);
        EMIT(3*j + 1, gpy[j]);
        EMIT(3*j + 2, gpz[j]);
    }
    #undef EMIT
}

extern "C" void kernel_launch(void* const* d_in, const int* in_sizes, int n_in,
                              void* d_out, int out_size)
{
    // metadata order: root_orientation_quat [B,4], root_position [B,3],
    //                 local_joint_rotations_quat [B,J,4], bone_lengths [B,J],
    //                 rest_directions [J,3]
    const float4* rootq  = (const float4*)d_in[0];
    const float*  rootp  = (const float*)d_in[1];
    const float4* localq = (const float4*)d_in[2];
    const float*  bl     = (const float*)d_in[3];
    const float*  restd  = (const float*)d_in[4];
    float*        out    = (float*)d_out;

    int nbatch = in_sizes[1] / 3;   // root_position has B*3 elements

    int blocks = (nbatch + TPB - 1) / TPB;
    fk_kernel<<<blocks, TPB>>>(rootq, rootp, localq, bl, restd, out, nbatch);
}

// round 7
// speedup vs baseline: 1.7912x; 1.0665x over previous
#include <cuda_runtime.h>
#include <math.h>

#define JN 24
#define EPSF 1e-8f
#define TPB 256

// R7: 256-bit LOADS to match the 256-bit stores that won R6.
//  - localq: per-thread region 384B, 32B-aligned -> 12 ld.global.v8.f32
//    (quat pairs (0,1),(2,3),... ; pair (0,1) includes unused quat 0 but the
//    line is fetched anyway -> no extra DRAM traffic).
//  - bl: 96B region, 32B-aligned -> 3 v8 loads.
// Per-thread LDG count 34 -> 19; each scoreboard wait now covers two loop
// iterations. Keep the proven 64-reg / 4-CTA operating point.

__device__ __forceinline__ void stg256(float* p, const float* v) {
    asm volatile(
        "st.global.v8.f32 [%0], {%1,%2,%3,%4,%5,%6,%7,%8};"
        :: "l"(p),
           "f"(v[0]), "f"(v[1]), "f"(v[2]), "f"(v[3]),
           "f"(v[4]), "f"(v[5]), "f"(v[6]), "f"(v[7])
        : "memory");
}

__device__ __forceinline__ void ldg256(const float* p, float* v) {
    asm volatile(
        "ld.global.v8.f32 {%0,%1,%2,%3,%4,%5,%6,%7}, [%8];"
        : "=f"(v[0]), "=f"(v[1]), "=f"(v[2]), "=f"(v[3]),
          "=f"(v[4]), "=f"(v[5]), "=f"(v[6]), "=f"(v[7])
        : "l"(p));
}

__global__ __launch_bounds__(TPB, 4) void fk_kernel(
    const float4* __restrict__ rootq,   // [B,4]  (w,x,y,z)
    const float*  __restrict__ rootp,   // [B,3]
    const float*  __restrict__ localq,  // [B,J,4] viewed as floats
    const float*  __restrict__ bl,      // [B,J]
    const float*  __restrict__ restd,   // [J,3]
    float*        __restrict__ out,     // [B,J,3]
    int nbatch)
{
    __shared__ float sdir[JN * 3];
    if (threadIdx.x < JN * 3) sdir[threadIdx.x] = restd[threadIdx.x];
    __syncthreads();

    const int b = blockIdx.x * TPB + threadIdx.x;
    if (b >= nbatch) return;

    const int PAR[JN] = {-1,0,0,0,1,2,3,4,5,6,7,8,9,9,9,12,13,14,16,17,18,19,20,21};

    // Hoist all 24 bone lengths as 3 independent v8 loads (MLP).
    float blv[JN];
    {
        const float* blb = bl + (size_t)b * JN;
        ldg256(blb,      blv);
        ldg256(blb + 8,  blv + 8);
        ldg256(blb + 16, blv + 16);
    }

    float gqw[JN], gqx[JN], gqy[JN], gqz[JN];
    float gpx[JN], gpy[JN], gpz[JN];

    // Root: normalize orientation quat; position passes through.
    {
        float4 rq = rootq[b];
        float s   = rq.x*rq.x + rq.y*rq.y + rq.z*rq.z + rq.w*rq.w;
        float inv = 1.0f / (sqrtf(s) + EPSF);
        gqw[0] = rq.x * inv;
        gqx[0] = rq.y * inv;
        gqy[0] = rq.z * inv;
        gqz[0] = rq.w * inv;
    }
    gpx[0] = rootp[3 * b + 0];
    gpy[0] = rootp[3 * b + 1];
    gpz[0] = rootp[3 * b + 2];

    // Rolling 8-float output buffer -> one st.global.v8.f32 per 8 floats.
    float sb[8];
    float* ob = out + (size_t)b * (JN * 3);

    #define EMIT(o, v)                                 \
        do {                                           \
            sb[(o) & 7] = (v);                         \
            if (((o) & 7) == 7)                        \
                stg256(ob + ((o) & ~7), sb);           \
        } while (0)

    EMIT(0, gpx[0]);
    EMIT(1, gpy[0]);
    EMIT(2, gpz[0]);

    const float* lqf = localq + (size_t)b * (JN * 4);

    // qpair holds quats (j, j+1) for even j; loaded at j=1 (pair 0,1) and at
    // every even j. Fully unrolled -> SSA, ptxas schedules the loads early.
    float qpair[8];

    #pragma unroll
    for (int j = 1; j < JN; j++) {
        const int p = PAR[j];

        // Load the aligned quat pair when entering it.
        if (j == 1) {
            ldg256(lqf, qpair);              // quats 0,1 (quat 0 unused)
        } else if ((j & 1) == 0) {
            ldg256(lqf + j * 4, qpair);      // quats j, j+1
        }
        const float* cq = qpair + ((j & 1) ? 4 : 0);

        // Normalize local quat for joint j.
        float s   = cq[0]*cq[0] + cq[1]*cq[1] + cq[2]*cq[2] + cq[3]*cq[3];
        float inv = 1.0f / (sqrtf(s) + EPSF);
        float cw = cq[0] * inv, cx = cq[1] * inv, cy = cq[2] * inv, cz = cq[3] * inv;

        // Parent global quat.
        float pw = gqw[p], px = gqx[p], py = gqy[p], pz = gqz[p];

        // Global quat for j = parent . local.
        gqw[j] = pw*cw - px*cx - py*cy - pz*cz;
        gqx[j] = pw*cx + px*cw + py*cz - pz*cy;
        gqy[j] = pw*cy - px*cz + py*cw + pz*cx;
        gqz[j] = pw*cz + px*cy - py*cx + pz*cw;

        // Rotate rest direction d[j] by the PARENT quat:
        // t = 2*cross(qvec, d); r = d + qw*t + cross(qvec, t)
        float dx = sdir[3*j + 0], dy = sdir[3*j + 1], dz = sdir[3*j + 2];
        float tx = 2.0f * (py*dz - pz*dy);
        float ty = 2.0f * (pz*dx - px*dz);
        float tz = 2.0f * (px*dy - py*dx);
        float rx = dx + pw*tx + (py*tz - pz*ty);
        float ry = dy + pw*ty + (pz*tx - px*tz);
        float rz = dz + pw*tz + (px*ty - py*tx);

        float L = blv[j];
        gpx[j] = gpx[p] + rx * L;
        gpy[j] = gpy[p] + ry * L;
        gpz[j] = gpz[p] + rz * L;

        EMIT(3*j + 0, gpx[j]);
        EMIT(3*j + 1, gpy[j]);
        EMIT(3*j + 2, gpz[j]);
    }
    #undef EMIT
}

extern "C" void kernel_launch(void* const* d_in, const int* in_sizes, int n_in,
                              void* d_out, int out_size)
{
    // metadata order: root_orientation_quat [B,4], root_position [B,3],
    //                 local_joint_rotations_quat [B,J,4], bone_lengths [B,J],
    //                 rest_directions [J,3]
    const float4* rootq  = (const float4*)d_in[0];
    const float*  rootp  = (const float*)d_in[1];
    const float*  localq = (const float*)d_in[2];
    const float*  bl     = (const float*)d_in[3];
    const float*  restd  = (const float*)d_in[4];
    float*        out    = (float*)d_out;

    int nbatch = in_sizes[1] / 3;   // root_position has B*3 elements

    int blocks = (nbatch + TPB - 1) / TPB;
    fk_kernel<<<blocks, TPB>>>(rootq, rootp, localq, bl, restd, out, nbatch);
}

// round 9
// speedup vs baseline: 2.0308x; 1.1337x over previous
#include <cuda_runtime.h>
#include <cstdint>
#include <math.h>

#define JN 24
#define EPSF 1e-8f
#define TPB 128

// R8b: cp.async (LDGSTS) staging of the local-quat stream into shared memory.
// Loads become fire-and-forget (no registers held, no per-warp scoreboard
// limit on MLP) -> DRAM BW is driven by the async queue, not occupancy.
//  - Block = 128 elements; localq block region is contiguous (128*384B).
//    Each thread issues 23 coalesced 16B cp.async (quat 0 is unused).
//  - Smem rows: 23 float4 = 368B/elem; word stride 92 (mod 32 = 28) ->
//    LDS.128 phases are bank-conflict-free without padding.
//  - bl/rootq/rootp stay direct LDGs, issued before the wait to overlap.
//  - Output: rolling 8-float buffer -> 9 st.global.v8.f32 per thread.

__device__ __forceinline__ void stg256(float* p, const float* v) {
    asm volatile(
        "st.global.v8.f32 [%0], {%1,%2,%3,%4,%5,%6,%7,%8};"
        :: "l"(p),
           "f"(v[0]), "f"(v[1]), "f"(v[2]), "f"(v[3]),
           "f"(v[4]), "f"(v[5]), "f"(v[6]), "f"(v[7])
        : "memory");
}

__device__ __forceinline__ void ldg256(const float* p, float* v) {
    asm volatile(
        "ld.global.v8.f32 {%0,%1,%2,%3,%4,%5,%6,%7}, [%8];"
        : "=f"(v[0]), "=f"(v[1]), "=f"(v[2]), "=f"(v[3]),
          "=f"(v[4]), "=f"(v[5]), "=f"(v[6]), "=f"(v[7])
        : "l"(p));
}

__device__ __forceinline__ void cp_async16(unsigned int smem_dst, const void* gsrc) {
    asm volatile("cp.async.cg.shared.global [%0], [%1], 16;"
                 :: "r"(smem_dst), "l"(gsrc) : "memory");
}

__global__ __launch_bounds__(TPB) void fk_kernel(
    const float4* __restrict__ rootq,   // [B,4]  (w,x,y,z)
    const float*  __restrict__ rootp,   // [B,3]
    const float*  __restrict__ localq,  // [B,J,4] as floats
    const float*  __restrict__ bl,      // [B,J]
    const float*  __restrict__ restd,   // [J,3]
    float*        __restrict__ out,     // [B,J,3]
    int nbatch)
{
    __shared__ float4 sq[TPB * 23];     // quats 1..23 per element, 368B rows
    __shared__ float  sdir[JN * 3];

    const int tid = threadIdx.x;
    if (tid < JN * 3) sdir[tid] = restd[tid];

    const int blk0 = blockIdx.x * TPB;
    const int b    = blk0 + tid;
    const bool active = (b < nbatch);

    // ---- Stage local quats 1..23 for all 128 elements via cp.async ----
    {
        unsigned int sq_base;
        asm("{ .reg .u64 t; cvta.to.shared.u64 t, %1; cvt.u32.u64 %0, t; }"
            : "=r"(sq_base) : "l"(sq));
        const float* lqb = localq + (size_t)blk0 * (JN * 4);

        #pragma unroll
        for (int k = 0; k < 23; k++) {
            int g = tid + k * TPB;          // 0..2943
            int e = g / 23;
            int j = 1 + (g - e * 23);       // 1..23
            if (blk0 + e < nbatch) {
                const float* src = lqb + e * (JN * 4) + j * 4;
                unsigned int dst = sq_base + (unsigned int)(e * 23 + (j - 1)) * 16u;
                cp_async16(dst, src);
            }
        }
        asm volatile("cp.async.commit_group;" ::: "memory");
    }

    // ---- Direct loads that overlap the async transfer ----
    float blv[JN];
    float gq0w, gq0x, gq0y, gq0z, gp0x, gp0y, gp0z;
    if (active) {
        const float* blb = bl + (size_t)b * JN;
        ldg256(blb,      blv);
        ldg256(blb + 8,  blv + 8);
        ldg256(blb + 16, blv + 16);

        float4 rq = rootq[b];
        float s   = rq.x*rq.x + rq.y*rq.y + rq.z*rq.z + rq.w*rq.w;
        float inv = 1.0f / (sqrtf(s) + EPSF);
        gq0w = rq.x * inv; gq0x = rq.y * inv; gq0y = rq.z * inv; gq0z = rq.w * inv;

        gp0x = rootp[3 * b + 0];
        gp0y = rootp[3 * b + 1];
        gp0z = rootp[3 * b + 2];
    }

    asm volatile("cp.async.wait_group 0;" ::: "memory");
    __syncthreads();

    if (!active) return;

    const int PAR[JN] = {-1,0,0,0,1,2,3,4,5,6,7,8,9,9,9,12,13,14,16,17,18,19,20,21};

    float gqw[JN], gqx[JN], gqy[JN], gqz[JN];
    float gpx[JN], gpy[JN], gpz[JN];
    gqw[0] = gq0w; gqx[0] = gq0x; gqy[0] = gq0y; gqz[0] = gq0z;
    gpx[0] = gp0x; gpy[0] = gp0y; gpz[0] = gp0z;

    // Rolling 8-float output buffer -> one st.global.v8.f32 per 8 floats.
    float sb[8];
    float* ob = out + (size_t)b * (JN * 3);

    #define EMIT(o, v)                                 \
        do {                                           \
            sb[(o) & 7] = (v);                         \
            if (((o) & 7) == 7)                        \
                stg256(ob + ((o) & ~7), sb);           \
        } while (0)

    EMIT(0, gpx[0]);
    EMIT(1, gpy[0]);
    EMIT(2, gpz[0]);

    const float4* qrow = sq + tid * 23;

    #pragma unroll
    for (int j = 1; j < JN; j++) {
        const int p = PAR[j];

        // Normalize local quat for joint j (from smem).
        float4 c4 = qrow[j - 1];
        float s   = c4.x*c4.x + c4.y*c4.y + c4.z*c4.z + c4.w*c4.w;
        float inv = 1.0f / (sqrtf(s) + EPSF);
        float cw = c4.x * inv, cx = c4.y * inv, cy = c4.z * inv, cz = c4.w * inv;

        // Parent global quat.
        float pw = gqw[p], px = gqx[p], py = gqy[p], pz = gqz[p];

        // Global quat for j = parent . local.
        gqw[j] = pw*cw - px*cx - py*cy - pz*cz;
        gqx[j] = pw*cx + px*cw + py*cz - pz*cy;
        gqy[j] = pw*cy - px*cz + py*cw + pz*cx;
        gqz[j] = pw*cz + px*cy - py*cx + pz*cw;

        // Rotate rest direction d[j] by the PARENT quat:
        // t = 2*cross(qvec, d); r = d + qw*t + cross(qvec, t)
        float dx = sdir[3*j + 0], dy = sdir[3*j + 1], dz = sdir[3*j + 2];
        float tx = 2.0f * (py*dz - pz*dy);
        float ty = 2.0f * (pz*dx - px*dz);
        float tz = 2.0f * (px*dy - py*dx);
        float rx = dx + pw*tx + (py*tz - pz*ty);
        float ry = dy + pw*ty + (pz*tx - px*tz);
        float rz = dz + pw*tz + (px*ty - py*tx);

        float L = blv[j];
        gpx[j] = gpx[p] + rx * L;
        gpy[j] = gpy[p] + ry * L;
        gpz[j] = gpz[p] + rz * L;

        EMIT(3*j + 0, gpx[j]);
        EMIT(3*j + 1, gpy[j]);
        EMIT(3*j + 2, gpz[j]);
    }
    #undef EMIT
}

extern "C" void kernel_launch(void* const* d_in, const int* in_sizes, int n_in,
                              void* d_out, int out_size)
{
    // metadata order: root_orientation_quat [B,4], root_position [B,3],
    //                 local_joint_rotations_quat [B,J,4], bone_lengths [B,J],
    //                 rest_directions [J,3]
    const float4* rootq  = (const float4*)d_in[0];
    const float*  rootp  = (const float*)d_in[1];
    const float*  localq = (const float*)d_in[2];
    const float*  bl     = (const float*)d_in[3];
    const float*  restd  = (const float*)d_in[4];
    float*        out    = (float*)d_out;

    int nbatch = in_sizes[1] / 3;   // root_position has B*3 elements

    int blocks = (nbatch + TPB - 1) / TPB;
    fk_kernel<<<blocks, TPB>>>(rootq, rootp, localq, bl, restd, out, nbatch);
}